// round 10
// baseline (speedup 1.0000x reference)
#include <cuda_runtime.h>
#include <cstdint>

// HDConvEncoder: 8-step depthwise-conv3 recurrence + LayerNorm(L) + pw scale/bias
// + GELU (A&S erf, abs err 2.5e-5) + residual. B=32, C=256, L=4096, S=8, Cs=32.
// One block per (b, c_local) chain (1024 blocks). Issue-bound kernel:
// packed f32x2 math everywhere + register diet (x re-read from SMEM) to hit
// 3 CTAs/SM. Conv neighbors via warp shuffles + per-warp SMEM edge scalars.
// R8 fix: lane-31 right tap of first half reads eA[wq0+1] (next chunk's first
// element), NOT the zero pad — wq0<=15 is never the final chunk.

#define NT 512
#define LLEN 4096
#define NG 8
#define CS 32
#define CTOT 256

typedef unsigned long long u64;

__device__ __forceinline__ uint32_t smem_u32(const void* p) {
    return (uint32_t)__cvta_generic_to_shared(p);
}
__device__ __forceinline__ u64 pk2(float lo, float hi) {
    u64 r;
    asm("mov.b64 %0, {%1, %2};" : "=l"(r) : "r"(__float_as_uint(lo)), "r"(__float_as_uint(hi)));
    return r;
}
__device__ __forceinline__ void upk2(u64 p, float& lo, float& hi) {
    uint32_t a, b;
    asm("mov.b64 {%0, %1}, %2;" : "=r"(a), "=r"(b) : "l"(p));
    lo = __uint_as_float(a); hi = __uint_as_float(b);
}
__device__ __forceinline__ u64 splat2(float v) { return pk2(v, v); }
__device__ __forceinline__ u64 fma2(u64 a, u64 b, u64 c) {
    u64 r; asm("fma.rn.f32x2 %0, %1, %2, %3;" : "=l"(r) : "l"(a), "l"(b), "l"(c)); return r;
}
__device__ __forceinline__ u64 mul2(u64 a, u64 b) {
    u64 r; asm("mul.rn.f32x2 %0, %1, %2;" : "=l"(r) : "l"(a), "l"(b)); return r;
}
__device__ __forceinline__ u64 add2(u64 a, u64 b) {
    u64 r; asm("add.rn.f32x2 %0, %1, %2;" : "=l"(r) : "l"(a), "l"(b)); return r;
}
__device__ __forceinline__ u64 abs2(u64 a) {
    u64 r; asm("and.b64 %0, %1, 0x7FFFFFFF7FFFFFFF;" : "=l"(r) : "l"(a)); return r;
}
__device__ __forceinline__ float frcp(float x) {
    float r; asm("rcp.approx.f32 %0, %1;" : "=f"(r) : "f"(x)); return r;
}
__device__ __forceinline__ float fex2(float x) {
    float r; asm("ex2.approx.f32 %0, %1;" : "=f"(r) : "f"(x)); return r;
}

// Packed LN+pw+gelu+residual for 2 elements. Constants as literals so ptxas can
// rematerialize rather than pin registers.
__device__ __forceinline__ u64 epilogue2(u64 Yj, u64 Xj, u64 Gj, u64 Bj,
                                         u64 RSTD, u64 C0, u64 PWW, u64 PWB) {
    const u64 ONE2 = splat2(1.0f);
    u64 T = fma2(fma2(fma2(Yj, RSTD, C0), Gj, Bj), PWW, PWB);
    u64 U  = abs2(T);
    u64 EA = mul2(mul2(T, T), splat2(-0.72134752f));   // -x^2*log2(e), x=T/sqrt2
    u64 D  = fma2(U, splat2(0.33267031f), ONE2);       // 1 + p*|x|
    float d0, d1, e0, e1;
    upk2(D, d0, d1); upk2(EA, e0, e1);
    u64 K = pk2(frcp(d0), frcp(d1));
    u64 E = pk2(fex2(e0), fex2(e1));
    u64 q = fma2(K, splat2(-0.7478556f), splat2(0.0958798f));
    q = fma2(K, q, splat2(-0.3480242f));
    u64 Gv = fma2(mul2(K, q), E, ONE2);                // erf(|x|)
    u64 R  = fma2(U, Gv, T);                           // T + |T|*erf
    return fma2(splat2(0.5f), R, Xj);                  // x + 0.5*(...)
}

__global__ void __launch_bounds__(NT, 3)
hdconv_encoder_kernel(const float* __restrict__ x,
                      const float* __restrict__ conv_w,   // [8,3,32]
                      const float* __restrict__ conv_b,   // [8,32]
                      const float* __restrict__ ln_g,     // [4096]
                      const float* __restrict__ ln_b,     // [4096]
                      const float* __restrict__ pw_w,     // [256]
                      const float* __restrict__ pw_b,     // [256]
                      float* __restrict__ out)
{
    extern __shared__ float sm[];
    float* sgam = sm;                  // 4096
    float* sbet = sm + LLEN;           // 4096
    float* xb0  = sm + 2 * LLEN;       // 4096 (x stage buf 0)
    float* xb1  = sm + 3 * LLEN;       // 4096 (x stage buf 1)
    float* eA   = sm + 4 * LLEN;       // 32 first-z per warp-chunk
    float* eB   = eA + 32;             // 32 last-z per warp-chunk
    float* red  = eB + 32;             // 32 (s,ss) partials

    const int tid  = threadIdx.x;
    const int lane = tid & 31;
    const int warp = tid >> 5;
    const int b    = blockIdx.x >> 5;
    const int cl   = blockIdx.x & 31;

    const float* xbase = x   + ((long)b * CTOT + cl) * LLEN;
    float*       obase = out + ((long)b * CTOT + cl) * LLEN;

    // gamma/beta -> SMEM (own-slot access only; no barrier needed).
    ((float4*)sgam)[tid]      = ((const float4*)ln_g)[tid];
    ((float4*)sgam)[tid + NT] = ((const float4*)ln_g)[tid + NT];
    ((float4*)sbet)[tid]      = ((const float4*)ln_b)[tid];
    ((float4*)sbet)[tid + NT] = ((const float4*)ln_b)[tid + NT];

    auto prefetch = [&](int i, float* buf) {
        const float* src = xbase + (long)i * CS * LLEN;
        uint32_t d0 = smem_u32(buf + 4 * tid);
        uint32_t d1 = smem_u32(buf + 4 * (tid + NT));
        asm volatile("cp.async.cg.shared.global [%0], [%1], 16;\n" :: "r"(d0), "l"(src + 4 * tid));
        asm volatile("cp.async.cg.shared.global [%0], [%1], 16;\n" :: "r"(d1), "l"(src + 4 * (tid + NT)));
        asm volatile("cp.async.commit_group;\n");
    };
    prefetch(0, xb0);

    u64 Y0 = 0ull, Y1 = 0ull, Y2 = 0ull, Y3 = 0ull;

    const int wq0 = tid >> 5;          // warp-chunk id of first half (0..15)
    const int wq1 = wq0 + 16;          // warp-chunk id of second half (16..31)

#pragma unroll 1
    for (int i = 0; i < NG; i++) {
        float* curb = (i & 1) ? xb1 : xb0;
        float* nxtb = (i & 1) ? xb0 : xb1;
        if (i < NG - 1) {
            prefetch(i + 1, nxtb);
            asm volatile("cp.async.wait_group 1;\n");
        } else {
            asm volatile("cp.async.wait_group 0;\n");
        }

        // z = x + y_prev (x read from SMEM, not kept in registers).
        {
            float4 xa = ((const float4*)curb)[tid];
            Y0 = add2(Y0, pk2(xa.x, xa.y));
            Y1 = add2(Y1, pk2(xa.z, xa.w));
            float4 xb = ((const float4*)curb)[tid + NT];
            Y2 = add2(Y2, pk2(xb.x, xb.y));
            Y3 = add2(Y3, pk2(xb.z, xb.w));
        }

        const float w0  = __ldg(conv_w + i * 96 + 0 * 32 + cl);
        const float w1  = __ldg(conv_w + i * 96 + 1 * 32 + cl);
        const float w2  = __ldg(conv_w + i * 96 + 2 * 32 + cl);
        const float bb  = __ldg(conv_b + i * 32 + cl);

        float z0, z1, z2, z3, z4_, z5, z6, z7;
        upk2(Y0, z0, z1); upk2(Y1, z2, z3);
        upk2(Y2, z4_, z5); upk2(Y3, z6, z7);

        if (lane == 0)  { eA[wq0] = z0; eA[wq1] = z4_; }
        if (lane == 31) { eB[wq0] = z3; eB[wq1] = z7; }
        __syncthreads();

        float zmw0 = __shfl_up_sync(0xFFFFFFFFu, z3, 1);
        float zpx0 = __shfl_down_sync(0xFFFFFFFFu, z0, 1);
        float zmw1 = __shfl_up_sync(0xFFFFFFFFu, z7, 1);
        float zpx1 = __shfl_down_sync(0xFFFFFFFFu, z4_, 1);
        // First half spans chunks 0..15: left edge of chunk 0 is the zero pad,
        // right neighbor of lane 31 ALWAYS exists (chunk wq0+1 <= 16).
        float zm0 = (lane == 0)  ? ((wq0 == 0) ? 0.f : eB[wq0 - 1]) : zmw0;
        float zp0 = (lane == 31) ? eA[wq0 + 1] : zpx0;
        // Second half spans chunks 16..31: left neighbor always exists,
        // right edge of chunk 31 is the zero pad.
        float zm1 = (lane == 0)  ? eB[wq1 - 1] : zmw1;
        float zp1 = (lane == 31) ? ((wq1 == 31) ? 0.f : eA[wq1 + 1]) : zpx1;

        // conv3 packed: Y = w0*zm + w1*zc + w2*zp + bb
        {
            const u64 W0 = splat2(w0), W1 = splat2(w1), W2 = splat2(w2), BB = splat2(bb);
            u64 t;
            u64 C01 = pk2(z1, z2);
            t = fma2(W2, C01, BB); t = fma2(W1, Y0, t); u64 n0 = fma2(W0, pk2(zm0, z0), t);
            t = fma2(W2, pk2(z3, zp0), BB); t = fma2(W1, Y1, t); Y1 = fma2(W0, C01, t);
            Y0 = n0;
            u64 C23 = pk2(z5, z6);
            t = fma2(W2, C23, BB); t = fma2(W1, Y2, t); u64 n2 = fma2(W0, pk2(zm1, z4_), t);
            t = fma2(W2, pk2(z7, zp1), BB); t = fma2(W1, Y3, t); Y3 = fma2(W0, C23, t);
            Y2 = n2;
        }

        // packed partial sums -> block reduction
        float s, ss;
        {
            u64 PS  = add2(add2(Y0, Y1), add2(Y2, Y3));
            u64 PSS = fma2(Y0, Y0, fma2(Y1, Y1, fma2(Y2, Y2, mul2(Y3, Y3))));
            float s0, s1, q0, q1;
            upk2(PS, s0, s1); upk2(PSS, q0, q1);
            s = s0 + s1; ss = q0 + q1;
        }
#pragma unroll
        for (int o = 16; o > 0; o >>= 1) {
            s  += __shfl_xor_sync(0xFFFFFFFFu, s,  o);
            ss += __shfl_xor_sync(0xFFFFFFFFu, ss, o);
        }
        if (lane == 0) { red[2 * warp] = s; red[2 * warp + 1] = ss; }
        __syncthreads();
        float a = (lane < 16) ? red[2 * lane]     : 0.f;
        float c = (lane < 16) ? red[2 * lane + 1] : 0.f;
#pragma unroll
        for (int o = 8; o > 0; o >>= 1) {
            a += __shfl_xor_sync(0xFFFFFFFFu, a, o);
            c += __shfl_xor_sync(0xFFFFFFFFu, c, o);
        }
        a = __shfl_sync(0xFFFFFFFFu, a, 0);
        c = __shfl_sync(0xFFFFFFFFu, c, 0);

        const float mean = a * (1.0f / (float)LLEN);
        const float rstd = rsqrtf(c * (1.0f / (float)LLEN) - mean * mean + 1e-6f);
        const u64 RSTD = splat2(rstd);
        const u64 C0   = splat2(-mean * rstd);
        const u64 PWW  = splat2(__ldg(pw_w + i * 32 + cl));
        const u64 PWB  = splat2(__ldg(pw_b + i * 32 + cl));

        // Epilogue half 0 (x/gamma/beta re-read from SMEM; tight transients).
        float* orow = obase + (long)i * CS * LLEN;
        {
            float4 xa = ((const float4*)curb)[tid];
            float4 g  = ((const float4*)sgam)[tid];
            float4 be = ((const float4*)sbet)[tid];
            u64 O0 = epilogue2(Y0, pk2(xa.x, xa.y), pk2(g.x, g.y), pk2(be.x, be.y), RSTD, C0, PWW, PWB);
            u64 O1 = epilogue2(Y1, pk2(xa.z, xa.w), pk2(g.z, g.w), pk2(be.z, be.w), RSTD, C0, PWW, PWB);
            float4 o;
            upk2(O0, o.x, o.y); upk2(O1, o.z, o.w);
            __stcs(((float4*)orow) + tid, o);
        }
        // Epilogue half 1.
        {
            float4 xb = ((const float4*)curb)[tid + NT];
            float4 g  = ((const float4*)sgam)[tid + NT];
            float4 be = ((const float4*)sbet)[tid + NT];
            u64 O2 = epilogue2(Y2, pk2(xb.x, xb.y), pk2(g.x, g.y), pk2(be.x, be.y), RSTD, C0, PWW, PWB);
            u64 O3 = epilogue2(Y3, pk2(xb.z, xb.w), pk2(g.z, g.w), pk2(be.z, be.w), RSTD, C0, PWW, PWB);
            float4 o;
            upk2(O2, o.x, o.y); upk2(O3, o.z, o.w);
            __stcs(((float4*)orow) + tid + NT, o);
        }
    }
}

extern "C" void kernel_launch(void* const* d_in, const int* in_sizes, int n_in,
                              void* d_out, int out_size)
{
    const float* x      = (const float*)d_in[0];
    const float* conv_w = (const float*)d_in[1];
    const float* conv_b = (const float*)d_in[2];
    const float* ln_g   = (const float*)d_in[3];
    const float* ln_b   = (const float*)d_in[4];
    const float* pw_w   = (const float*)d_in[5];
    const float* pw_b   = (const float*)d_in[6];
    float* out = (float*)d_out;

    const int smem_bytes = (4 * LLEN + 96) * (int)sizeof(float); // 65920
    cudaFuncSetAttribute(hdconv_encoder_kernel,
                         cudaFuncAttributeMaxDynamicSharedMemorySize, smem_bytes);

    dim3 grid(32 * 32);
    dim3 block(NT);
    hdconv_encoder_kernel<<<grid, block, smem_bytes>>>(
        x, conv_w, conv_b, ln_g, ln_b, pw_w, pw_b, out);
}

// round 11
// speedup vs baseline: 1.4079x; 1.4079x over previous
#include <cuda_runtime.h>
#include <cstdint>

// HDConvEncoder: 8-step depthwise-conv3 recurrence + LayerNorm(L) + pw scale/bias
// + GELU (A&S erf) + residual. B=32, C=256, L=4096, S=8, Cs=32.
// One block per (b,c_local) chain (1024 blocks). R3 structure (packed f32x2,
// X in registers, occ-2) + single-barrier iterations: next-iter conv edges are
// published early (post-conv, own-thread cp.async data) and ride the reduction
// barrier; edge/partial buffers double-buffered by iteration parity.

#define NT 512
#define LLEN 4096
#define NG 8
#define CS 32
#define CTOT 256

typedef unsigned long long u64;

__device__ __forceinline__ uint32_t smem_u32(const void* p) {
    return (uint32_t)__cvta_generic_to_shared(p);
}
__device__ __forceinline__ u64 pk2(float lo, float hi) {
    u64 r;
    asm("mov.b64 %0, {%1, %2};" : "=l"(r) : "r"(__float_as_uint(lo)), "r"(__float_as_uint(hi)));
    return r;
}
__device__ __forceinline__ void upk2(u64 p, float& lo, float& hi) {
    uint32_t a, b;
    asm("mov.b64 {%0, %1}, %2;" : "=r"(a), "=r"(b) : "l"(p));
    lo = __uint_as_float(a); hi = __uint_as_float(b);
}
__device__ __forceinline__ u64 splat2(float v) { return pk2(v, v); }
__device__ __forceinline__ u64 fma2(u64 a, u64 b, u64 c) {
    u64 r; asm("fma.rn.f32x2 %0, %1, %2, %3;" : "=l"(r) : "l"(a), "l"(b), "l"(c)); return r;
}
__device__ __forceinline__ u64 mul2(u64 a, u64 b) {
    u64 r; asm("mul.rn.f32x2 %0, %1, %2;" : "=l"(r) : "l"(a), "l"(b)); return r;
}
__device__ __forceinline__ u64 add2(u64 a, u64 b) {
    u64 r; asm("add.rn.f32x2 %0, %1, %2;" : "=l"(r) : "l"(a), "l"(b)); return r;
}
__device__ __forceinline__ u64 abs2(u64 a) {
    u64 r; asm("and.b64 %0, %1, 0x7FFFFFFF7FFFFFFF;" : "=l"(r) : "l"(a)); return r;
}
__device__ __forceinline__ float frcp(float x) {
    float r; asm("rcp.approx.f32 %0, %1;" : "=f"(r) : "f"(x)); return r;
}
__device__ __forceinline__ float fex2(float x) {
    float r; asm("ex2.approx.f32 %0, %1;" : "=f"(r) : "f"(x)); return r;
}

// Packed LN+pw+gelu+residual for 2 elements (A&S 7.1.26 erf, abs err 2.5e-5).
__device__ __forceinline__ u64 epilogue2(u64 Yj, u64 Xj, u64 Gj, u64 Bj,
                                         u64 RSTD, u64 C0, u64 PWW, u64 PWB) {
    const u64 ONE2 = splat2(1.0f);
    u64 T = fma2(fma2(fma2(Yj, RSTD, C0), Gj, Bj), PWW, PWB);
    u64 U  = abs2(T);
    u64 EA = mul2(mul2(T, T), splat2(-0.72134752f));   // -x^2*log2(e), x=T/sqrt2
    u64 D  = fma2(U, splat2(0.33267031f), ONE2);       // 1 + p*|x|
    float d0, d1, e0, e1;
    upk2(D, d0, d1); upk2(EA, e0, e1);
    u64 K = pk2(frcp(d0), frcp(d1));
    u64 E = pk2(fex2(e0), fex2(e1));
    u64 q = fma2(K, splat2(-0.7478556f), splat2(0.0958798f));
    q = fma2(K, q, splat2(-0.3480242f));
    u64 Gv = fma2(mul2(K, q), E, ONE2);                // erf(|x|)
    u64 R  = fma2(U, Gv, T);                           // T + |T|*erf
    return fma2(splat2(0.5f), R, Xj);                  // x + 0.5*(...)
}

__global__ void __launch_bounds__(NT, 2)
hdconv_encoder_kernel(const float* __restrict__ x,
                      const float* __restrict__ conv_w,   // [8,3,32]
                      const float* __restrict__ conv_b,   // [8,32]
                      const float* __restrict__ ln_g,     // [4096]
                      const float* __restrict__ ln_b,     // [4096]
                      const float* __restrict__ pw_w,     // [256]
                      const float* __restrict__ pw_b,     // [256]
                      float* __restrict__ out)
{
    extern __shared__ float sm[];
    float* sgam = sm;                  // 4096
    float* sbet = sm + LLEN;           // 4096
    float* xb0  = sm + 2 * LLEN;       // 4096 (x stage buf 0)
    float* xb1  = sm + 3 * LLEN;       // 4096 (x stage buf 1)
    float* eA   = sm + 4 * LLEN;       // [2][32] first-z per chunk, per parity
    float* eB   = eA + 64;             // [2][32] last-z per chunk, per parity
    float* red  = eB + 64;             // [2][32] (s,ss) partials, per parity

    const int tid  = threadIdx.x;
    const int lane = tid & 31;
    const int warp = tid >> 5;
    const int b    = blockIdx.x >> 5;
    const int cl   = blockIdx.x & 31;

    const float* xbase = x   + ((long)b * CTOT + cl) * LLEN;
    float*       obase = out + ((long)b * CTOT + cl) * LLEN;

    // gamma/beta -> SMEM (own-slot access only).
    ((float4*)sgam)[tid]      = ((const float4*)ln_g)[tid];
    ((float4*)sgam)[tid + NT] = ((const float4*)ln_g)[tid + NT];
    ((float4*)sbet)[tid]      = ((const float4*)ln_b)[tid];
    ((float4*)sbet)[tid + NT] = ((const float4*)ln_b)[tid + NT];

    auto prefetch = [&](int i, float* buf) {
        const float* src = xbase + (long)i * CS * LLEN;
        uint32_t d0 = smem_u32(buf + 4 * tid);
        uint32_t d1 = smem_u32(buf + 4 * (tid + NT));
        asm volatile("cp.async.cg.shared.global [%0], [%1], 16;\n" :: "r"(d0), "l"(src + 4 * tid));
        asm volatile("cp.async.cg.shared.global [%0], [%1], 16;\n" :: "r"(d1), "l"(src + 4 * (tid + NT)));
        asm volatile("cp.async.commit_group;\n");
    };

    const int wq0 = tid >> 5;          // chunk id of first half (0..15)
    const int wq1 = wq0 + 16;          // chunk id of second half (16..31)

    prefetch(0, xb0);
    asm volatile("cp.async.wait_group 0;\n");
    // Iter-0 edges: y_prev = 0 -> edge z = x. Own-thread cp.async data.
    if (lane == 0) {
        eA[wq0] = xb0[wq0 * 128];
        eA[wq1] = xb0[wq1 * 128];
    }
    if (lane == 31) {
        eB[wq0] = xb0[wq0 * 128 + 127];
        eB[wq1] = xb0[wq1 * 128 + 127];
    }
    prefetch(1, xb1);
    __syncthreads();  // edges + gamma/beta visible

    u64 Y0 = 0ull, Y1 = 0ull, Y2 = 0ull, Y3 = 0ull;

#pragma unroll 1
    for (int i = 0; i < NG; i++) {
        const int p = i & 1;
        float* curb = p ? xb1 : xb0;
        float* nxtb = p ? xb0 : xb1;
        float* eAp = eA + p * 32;
        float* eBp = eB + p * 32;

        // x for this group from own SMEM slots (data waited in prev iteration).
        u64 X0, X1, X2, X3;
        {
            float4 xa = ((const float4*)curb)[tid];
            X0 = pk2(xa.x, xa.y); X1 = pk2(xa.z, xa.w);
            float4 xb = ((const float4*)curb)[tid + NT];
            X2 = pk2(xb.x, xb.y); X3 = pk2(xb.z, xb.w);
        }
        // z = x + y_prev
        Y0 = add2(Y0, X0); Y1 = add2(Y1, X1);
        Y2 = add2(Y2, X2); Y3 = add2(Y3, X3);

        const float w0  = __ldg(conv_w + i * 96 + 0 * 32 + cl);
        const float w1  = __ldg(conv_w + i * 96 + 1 * 32 + cl);
        const float w2  = __ldg(conv_w + i * 96 + 2 * 32 + cl);
        const float bb  = __ldg(conv_b + i * 32 + cl);

        float z0, z1, z2, z3, z4_, z5, z6, z7;
        upk2(Y0, z0, z1); upk2(Y1, z2, z3);
        upk2(Y2, z4_, z5); upk2(Y3, z6, z7);

        float zmw0 = __shfl_up_sync(0xFFFFFFFFu, z3, 1);
        float zpx0 = __shfl_down_sync(0xFFFFFFFFu, z0, 1);
        float zmw1 = __shfl_up_sync(0xFFFFFFFFu, z7, 1);
        float zpx1 = __shfl_down_sync(0xFFFFFFFFu, z4_, 1);
        // Edges from parity-p buffers (published at previous iteration's barrier).
        float zm0 = (lane == 0)  ? ((wq0 == 0) ? 0.f : eBp[wq0 - 1]) : zmw0;
        float zp0 = (lane == 31) ? eAp[wq0 + 1] : zpx0;               // wq0<=15: next chunk exists
        float zm1 = (lane == 0)  ? eBp[wq1 - 1] : zmw1;               // wq1>=16: prev chunk exists
        float zp1 = (lane == 31) ? ((wq1 == 31) ? 0.f : eAp[wq1 + 1]) : zpx1;

        // conv3 packed: Y = w0*zm + w1*zc + w2*zp + bb
        {
            const u64 W0 = splat2(w0), W1 = splat2(w1), W2 = splat2(w2), BB = splat2(bb);
            u64 t;
            u64 C01 = pk2(z1, z2);
            t = fma2(W2, C01, BB); t = fma2(W1, Y0, t); u64 n0 = fma2(W0, pk2(zm0, z0), t);
            t = fma2(W2, pk2(z3, zp0), BB); t = fma2(W1, Y1, t); Y1 = fma2(W0, C01, t);
            Y0 = n0;
            u64 C23 = pk2(z5, z6);
            t = fma2(W2, C23, BB); t = fma2(W1, Y2, t); u64 n2 = fma2(W0, pk2(zm1, z4_), t);
            t = fma2(W2, pk2(z7, zp1), BB); t = fma2(W1, Y3, t); Y3 = fma2(W0, C23, t);
            Y2 = n2;
        }

        // Publish next iteration's edges: z_{i+1}[edge] = x_{i+1}[edge] + y_i[edge].
        // nxtb edge slots are this thread's own cp.async data -> wait_group suffices.
        if (i < NG - 1) {
            asm volatile("cp.async.wait_group 0;\n");
            if (lane == 0) {
                float ylo0, ylo1, t_;
                upk2(Y0, ylo0, t_);
                upk2(Y2, ylo1, t_);
                eA[(p ^ 1) * 32 + wq0] = nxtb[wq0 * 128] + ylo0;
                eA[(p ^ 1) * 32 + wq1] = nxtb[wq1 * 128] + ylo1;
            }
            if (lane == 31) {
                float yhi0, yhi1, t_;
                upk2(Y1, t_, yhi0);
                upk2(Y3, t_, yhi1);
                eB[(p ^ 1) * 32 + wq0] = nxtb[wq0 * 128 + 127] + yhi0;
                eB[(p ^ 1) * 32 + wq1] = nxtb[wq1 * 128 + 127] + yhi1;
            }
        }

        // Packed partial sums -> warp reduce -> parity-p partial slots.
        float s, ss;
        {
            u64 PS  = add2(add2(Y0, Y1), add2(Y2, Y3));
            u64 PSS = fma2(Y0, Y0, fma2(Y1, Y1, fma2(Y2, Y2, mul2(Y3, Y3))));
            float s0, s1, q0, q1;
            upk2(PS, s0, s1); upk2(PSS, q0, q1);
            s = s0 + s1; ss = q0 + q1;
        }
#pragma unroll
        for (int o = 16; o > 0; o >>= 1) {
            s  += __shfl_xor_sync(0xFFFFFFFFu, s,  o);
            ss += __shfl_xor_sync(0xFFFFFFFFu, ss, o);
        }
        float* redp = red + p * 32;
        if (lane == 0) { redp[2 * warp] = s; redp[2 * warp + 1] = ss; }

        __syncthreads();  // single barrier: publishes edges + partials

        // Early prefetch of group i+2 into curb (all X reads of curb done by barrier).
        if (i < NG - 2) prefetch(i + 2, curb);

        // Every warp redundantly reduces the 16 partials.
        float a = (lane < 16) ? redp[2 * lane]     : 0.f;
        float c = (lane < 16) ? redp[2 * lane + 1] : 0.f;
#pragma unroll
        for (int o = 8; o > 0; o >>= 1) {
            a += __shfl_xor_sync(0xFFFFFFFFu, a, o);
            c += __shfl_xor_sync(0xFFFFFFFFu, c, o);
        }
        a = __shfl_sync(0xFFFFFFFFu, a, 0);
        c = __shfl_sync(0xFFFFFFFFu, c, 0);

        const float mean = a * (1.0f / (float)LLEN);
        const float rstd = rsqrtf(c * (1.0f / (float)LLEN) - mean * mean + 1e-6f);
        const u64 RSTD = splat2(rstd);
        const u64 C0   = splat2(-mean * rstd);
        const u64 PWW  = splat2(__ldg(pw_w + i * 32 + cl));
        const u64 PWB  = splat2(__ldg(pw_b + i * 32 + cl));

        // Epilogue (X from registers, gamma/beta from SMEM own slots).
        float* orow = obase + (long)i * CS * LLEN;
        {
            float4 g  = ((const float4*)sgam)[tid];
            float4 be = ((const float4*)sbet)[tid];
            u64 O0 = epilogue2(Y0, X0, pk2(g.x, g.y), pk2(be.x, be.y), RSTD, C0, PWW, PWB);
            u64 O1 = epilogue2(Y1, X1, pk2(g.z, g.w), pk2(be.z, be.w), RSTD, C0, PWW, PWB);
            float4 o;
            upk2(O0, o.x, o.y); upk2(O1, o.z, o.w);
            __stcs(((float4*)orow) + tid, o);
        }
        {
            float4 g  = ((const float4*)sgam)[tid + NT];
            float4 be = ((const float4*)sbet)[tid + NT];
            u64 O2 = epilogue2(Y2, X2, pk2(g.x, g.y), pk2(be.x, be.y), RSTD, C0, PWW, PWB);
            u64 O3 = epilogue2(Y3, X3, pk2(g.z, g.w), pk2(be.z, be.w), RSTD, C0, PWW, PWB);
            float4 o;
            upk2(O2, o.x, o.y); upk2(O3, o.z, o.w);
            __stcs(((float4*)orow) + tid + NT, o);
        }
    }
}

extern "C" void kernel_launch(void* const* d_in, const int* in_sizes, int n_in,
                              void* d_out, int out_size)
{
    const float* x      = (const float*)d_in[0];
    const float* conv_w = (const float*)d_in[1];
    const float* conv_b = (const float*)d_in[2];
    const float* ln_g   = (const float*)d_in[3];
    const float* ln_b   = (const float*)d_in[4];
    const float* pw_w   = (const float*)d_in[5];
    const float* pw_b   = (const float*)d_in[6];
    float* out = (float*)d_out;

    const int smem_bytes = (4 * LLEN + 192) * (int)sizeof(float); // 66304
    cudaFuncSetAttribute(hdconv_encoder_kernel,
                         cudaFuncAttributeMaxDynamicSharedMemorySize, smem_bytes);

    dim3 grid(32 * 32);
    dim3 block(NT);
    hdconv_encoder_kernel<<<grid, block, smem_bytes>>>(
        x, conv_w, conv_b, ln_g, ln_b, pw_w, pw_b, out);
}

// round 12
// speedup vs baseline: 1.5669x; 1.1129x over previous
#include <cuda_runtime.h>
#include <cstdint>

// HDConvEncoder: 8-step depthwise-conv3 recurrence + LayerNorm(L) + pw scale/bias
// + GELU + residual. B=32, C=256, L=4096, S=8, Cs=32.
// One block per (b,c_local) chain (1024 blocks). R3 skeleton (packed f32x2, X in
// regs, occ 2, full-iteration cp.async prefetch distance) with:
//  - erf via A&S 7.1.28 (1 - w^-16): 2 MUFU/pair instead of 4 (no ex2), err 3e-7
//  - all 48 per-block weight scalars hoisted to SMEM once (LDS instead of LDG
//    at every iteration head)

#define NT 512
#define LLEN 4096
#define NG 8
#define CS 32
#define CTOT 256

typedef unsigned long long u64;

__device__ __forceinline__ uint32_t smem_u32(const void* p) {
    return (uint32_t)__cvta_generic_to_shared(p);
}
__device__ __forceinline__ u64 pk2(float lo, float hi) {
    u64 r;
    asm("mov.b64 %0, {%1, %2};" : "=l"(r) : "r"(__float_as_uint(lo)), "r"(__float_as_uint(hi)));
    return r;
}
__device__ __forceinline__ void upk2(u64 p, float& lo, float& hi) {
    uint32_t a, b;
    asm("mov.b64 {%0, %1}, %2;" : "=r"(a), "=r"(b) : "l"(p));
    lo = __uint_as_float(a); hi = __uint_as_float(b);
}
__device__ __forceinline__ u64 splat2(float v) { return pk2(v, v); }
__device__ __forceinline__ u64 fma2(u64 a, u64 b, u64 c) {
    u64 r; asm("fma.rn.f32x2 %0, %1, %2, %3;" : "=l"(r) : "l"(a), "l"(b), "l"(c)); return r;
}
__device__ __forceinline__ u64 mul2(u64 a, u64 b) {
    u64 r; asm("mul.rn.f32x2 %0, %1, %2;" : "=l"(r) : "l"(a), "l"(b)); return r;
}
__device__ __forceinline__ u64 add2(u64 a, u64 b) {
    u64 r; asm("add.rn.f32x2 %0, %1, %2;" : "=l"(r) : "l"(a), "l"(b)); return r;
}
__device__ __forceinline__ u64 abs2(u64 a) {
    u64 r; asm("and.b64 %0, %1, 0x7FFFFFFF7FFFFFFF;" : "=l"(r) : "l"(a)); return r;
}
__device__ __forceinline__ float frcp(float x) {
    float r; asm("rcp.approx.f32 %0, %1;" : "=f"(r) : "f"(x)); return r;
}

// Packed LN+pw+gelu+residual for 2 elements.
// gelu(T) = 0.5*(T + |T|*erf(|T|/sqrt2)); erf via A&S 7.1.28 (abs err 3e-7):
// erf(x) = 1 - (1 + a1 x + ... + a6 x^6)^-16, x>=0, with sqrt2 folded into coeffs.
__device__ __forceinline__ u64 epilogue2(u64 Yj, u64 Xj, u64 Gj, u64 Bj,
                                         u64 RSTD, u64 C0, u64 PWW, u64 PWB) {
    const u64 ONE2 = splat2(1.0f);
    u64 T = fma2(fma2(fma2(Yj, RSTD, C0), Gj, Bj), PWW, PWB);
    u64 U = abs2(T);
    u64 w = fma2(U, splat2(5.38298e-6f),  splat2(4.88910e-5f));
    w = fma2(U, w, splat2(3.80036e-5f));
    w = fma2(U, w, splat2(0.00327768f));
    w = fma2(U, w, splat2(0.02114101f));
    w = fma2(U, w, splat2(0.04986735f));
    w = fma2(U, w, ONE2);
    u64 w2  = mul2(w,  w);
    u64 w4  = mul2(w2, w2);
    u64 w8  = mul2(w4, w4);
    u64 w16 = mul2(w8, w8);
    float r0, r1;
    upk2(w16, r0, r1);
    u64 RI  = pk2(frcp(r0), frcp(r1));       // w^-16 (overflow -> 0 -> erf=1)
    u64 ERF = fma2(RI, splat2(-1.0f), ONE2); // 1 - w^-16
    u64 R   = fma2(U, ERF, T);               // T + |T|*erf
    return fma2(splat2(0.5f), R, Xj);        // x + 0.5*(...)
}

__global__ void __launch_bounds__(NT, 2)
hdconv_encoder_kernel(const float* __restrict__ x,
                      const float* __restrict__ conv_w,   // [8,3,32]
                      const float* __restrict__ conv_b,   // [8,32]
                      const float* __restrict__ ln_g,     // [4096]
                      const float* __restrict__ ln_b,     // [4096]
                      const float* __restrict__ pw_w,     // [256]
                      const float* __restrict__ pw_b,     // [256]
                      float* __restrict__ out)
{
    extern __shared__ float sm[];
    float* sgam = sm;                  // 4096
    float* sbet = sm + LLEN;           // 4096
    float* xb0  = sm + 2 * LLEN;       // 4096 (x stage buf 0)
    float* xb1  = sm + 3 * LLEN;       // 4096 (x stage buf 1)
    float* eA   = sm + 4 * LLEN;       // 32 first-z per warp-chunk
    float* eB   = eA + 32;             // 32 last-z per warp-chunk
    float* red  = eB + 32;             // 32 (s,ss) partials
    float* swt  = red + 32;            // 48 per-block weight scalars [g*6 + k]

    const int tid  = threadIdx.x;
    const int lane = tid & 31;
    const int warp = tid >> 5;
    const int b    = blockIdx.x >> 5;
    const int cl   = blockIdx.x & 31;

    const float* xbase = x   + ((long)b * CTOT + cl) * LLEN;
    float*       obase = out + ((long)b * CTOT + cl) * LLEN;

    // gamma/beta -> SMEM (own-slot access only; rides the pre-loop barrier).
    ((float4*)sgam)[tid]      = ((const float4*)ln_g)[tid];
    ((float4*)sgam)[tid + NT] = ((const float4*)ln_g)[tid + NT];
    ((float4*)sbet)[tid]      = ((const float4*)ln_b)[tid];
    ((float4*)sbet)[tid + NT] = ((const float4*)ln_b)[tid + NT];

    // Hoist ALL per-block weight scalars (8 groups x 6) into SMEM once.
    if (tid < NG) {
        const int g = tid;
        swt[g * 6 + 0] = conv_w[g * 96 +  0 + cl];
        swt[g * 6 + 1] = conv_w[g * 96 + 32 + cl];
        swt[g * 6 + 2] = conv_w[g * 96 + 64 + cl];
        swt[g * 6 + 3] = conv_b[g * 32 + cl];
        swt[g * 6 + 4] = pw_w[g * 32 + cl];
        swt[g * 6 + 5] = pw_b[g * 32 + cl];
    }

    auto prefetch = [&](int i, float* buf) {
        const float* src = xbase + (long)i * CS * LLEN;
        uint32_t d0 = smem_u32(buf + 4 * tid);
        uint32_t d1 = smem_u32(buf + 4 * (tid + NT));
        asm volatile("cp.async.cg.shared.global [%0], [%1], 16;\n" :: "r"(d0), "l"(src + 4 * tid));
        asm volatile("cp.async.cg.shared.global [%0], [%1], 16;\n" :: "r"(d1), "l"(src + 4 * (tid + NT)));
        asm volatile("cp.async.commit_group;\n");
    };
    prefetch(0, xb0);

    u64 Y0 = 0ull, Y1 = 0ull, Y2 = 0ull, Y3 = 0ull;

    const int wq0 = tid >> 5;          // warp-chunk id of first half (0..15)
    const int wq1 = wq0 + 16;          // warp-chunk id of second half (16..31)

    __syncthreads(); // gamma/beta + swt visible

#pragma unroll 1
    for (int i = 0; i < NG; i++) {
        float* curb = (i & 1) ? xb1 : xb0;
        float* nxtb = (i & 1) ? xb0 : xb1;
        if (i < NG - 1) {
            prefetch(i + 1, nxtb);
            asm volatile("cp.async.wait_group 1;\n");   // wait for THIS iter's data
        } else {
            asm volatile("cp.async.wait_group 0;\n");
        }

        // x for this group from own SMEM slots.
        u64 X0, X1, X2, X3;
        {
            float4 xa = ((const float4*)curb)[tid];
            X0 = pk2(xa.x, xa.y); X1 = pk2(xa.z, xa.w);
            float4 xb = ((const float4*)curb)[tid + NT];
            X2 = pk2(xb.x, xb.y); X3 = pk2(xb.z, xb.w);
        }
        // z = x + y_prev
        Y0 = add2(Y0, X0); Y1 = add2(Y1, X1);
        Y2 = add2(Y2, X2); Y3 = add2(Y3, X3);

        // Per-group scalars: broadcast LDS (hoisted at block start).
        const float w0 = swt[i * 6 + 0];
        const float w1 = swt[i * 6 + 1];
        const float w2 = swt[i * 6 + 2];
        const float bb = swt[i * 6 + 3];

        float z0, z1, z2, z3, z4_, z5, z6, z7;
        upk2(Y0, z0, z1); upk2(Y1, z2, z3);
        upk2(Y2, z4_, z5); upk2(Y3, z6, z7);

        if (lane == 0)  { eA[wq0] = z0; eA[wq1] = z4_; }
        if (lane == 31) { eB[wq0] = z3; eB[wq1] = z7; }
        __syncthreads();

        float zmw0 = __shfl_up_sync(0xFFFFFFFFu, z3, 1);
        float zpx0 = __shfl_down_sync(0xFFFFFFFFu, z0, 1);
        float zmw1 = __shfl_up_sync(0xFFFFFFFFu, z7, 1);
        float zpx1 = __shfl_down_sync(0xFFFFFFFFu, z4_, 1);
        // First half spans chunks 0..15: left edge of chunk 0 is zero pad,
        // lane-31 right neighbor always exists (chunk wq0+1 <= 16).
        float zm0 = (lane == 0)  ? ((wq0 == 0) ? 0.f : eB[wq0 - 1]) : zmw0;
        float zp0 = (lane == 31) ? eA[wq0 + 1] : zpx0;
        // Second half spans chunks 16..31: left neighbor always exists,
        // right edge of chunk 31 is zero pad.
        float zm1 = (lane == 0)  ? eB[wq1 - 1] : zmw1;
        float zp1 = (lane == 31) ? ((wq1 == 31) ? 0.f : eA[wq1 + 1]) : zpx1;

        // conv3 packed: Y = w0*zm + w1*zc + w2*zp + bb
        {
            const u64 W0 = splat2(w0), W1 = splat2(w1), W2 = splat2(w2), BB = splat2(bb);
            u64 t;
            u64 C01 = pk2(z1, z2);
            t = fma2(W2, C01, BB); t = fma2(W1, Y0, t); u64 n0 = fma2(W0, pk2(zm0, z0), t);
            t = fma2(W2, pk2(z3, zp0), BB); t = fma2(W1, Y1, t); Y1 = fma2(W0, C01, t);
            Y0 = n0;
            u64 C23 = pk2(z5, z6);
            t = fma2(W2, C23, BB); t = fma2(W1, Y2, t); u64 n2 = fma2(W0, pk2(zm1, z4_), t);
            t = fma2(W2, pk2(z7, zp1), BB); t = fma2(W1, Y3, t); Y3 = fma2(W0, C23, t);
            Y2 = n2;
        }

        // Packed partial sums -> warp reduce -> SMEM partials.
        float s, ss;
        {
            u64 PS  = add2(add2(Y0, Y1), add2(Y2, Y3));
            u64 PSS = fma2(Y0, Y0, fma2(Y1, Y1, fma2(Y2, Y2, mul2(Y3, Y3))));
            float s0, s1, q0, q1;
            upk2(PS, s0, s1); upk2(PSS, q0, q1);
            s = s0 + s1; ss = q0 + q1;
        }
#pragma unroll
        for (int o = 16; o > 0; o >>= 1) {
            s  += __shfl_xor_sync(0xFFFFFFFFu, s,  o);
            ss += __shfl_xor_sync(0xFFFFFFFFu, ss, o);
        }
        if (lane == 0) { red[2 * warp] = s; red[2 * warp + 1] = ss; }
        __syncthreads();
        // Every warp redundantly reduces the 16 partials (no broadcast barrier).
        float a = (lane < 16) ? red[2 * lane]     : 0.f;
        float c = (lane < 16) ? red[2 * lane + 1] : 0.f;
#pragma unroll
        for (int o = 8; o > 0; o >>= 1) {
            a += __shfl_xor_sync(0xFFFFFFFFu, a, o);
            c += __shfl_xor_sync(0xFFFFFFFFu, c, o);
        }
        a = __shfl_sync(0xFFFFFFFFu, a, 0);
        c = __shfl_sync(0xFFFFFFFFu, c, 0);

        const float mean = a * (1.0f / (float)LLEN);
        const float rstd = rsqrtf(c * (1.0f / (float)LLEN) - mean * mean + 1e-6f);
        const u64 RSTD = splat2(rstd);
        const u64 C0   = splat2(-mean * rstd);
        const u64 PWW  = splat2(swt[i * 6 + 4]);
        const u64 PWB  = splat2(swt[i * 6 + 5]);

        // Epilogue (X from registers, gamma/beta from SMEM own slots).
        float* orow = obase + (long)i * CS * LLEN;
        {
            float4 g  = ((const float4*)sgam)[tid];
            float4 be = ((const float4*)sbet)[tid];
            u64 O0 = epilogue2(Y0, X0, pk2(g.x, g.y), pk2(be.x, be.y), RSTD, C0, PWW, PWB);
            u64 O1 = epilogue2(Y1, X1, pk2(g.z, g.w), pk2(be.z, be.w), RSTD, C0, PWW, PWB);
            float4 o;
            upk2(O0, o.x, o.y); upk2(O1, o.z, o.w);
            __stcs(((float4*)orow) + tid, o);
        }
        {
            float4 g  = ((const float4*)sgam)[tid + NT];
            float4 be = ((const float4*)sbet)[tid + NT];
            u64 O2 = epilogue2(Y2, X2, pk2(g.x, g.y), pk2(be.x, be.y), RSTD, C0, PWW, PWB);
            u64 O3 = epilogue2(Y3, X3, pk2(g.z, g.w), pk2(be.z, be.w), RSTD, C0, PWW, PWB);
            float4 o;
            upk2(O2, o.x, o.y); upk2(O3, o.z, o.w);
            __stcs(((float4*)orow) + tid + NT, o);
        }
    }
}

extern "C" void kernel_launch(void* const* d_in, const int* in_sizes, int n_in,
                              void* d_out, int out_size)
{
    const float* x      = (const float*)d_in[0];
    const float* conv_w = (const float*)d_in[1];
    const float* conv_b = (const float*)d_in[2];
    const float* ln_g   = (const float*)d_in[3];
    const float* ln_b   = (const float*)d_in[4];
    const float* pw_w   = (const float*)d_in[5];
    const float* pw_b   = (const float*)d_in[6];
    float* out = (float*)d_out;

    const int smem_bytes = (4 * LLEN + 160) * (int)sizeof(float); // 66176
    cudaFuncSetAttribute(hdconv_encoder_kernel,
                         cudaFuncAttributeMaxDynamicSharedMemorySize, smem_bytes);

    dim3 grid(32 * 32);
    dim3 block(NT);
    hdconv_encoder_kernel<<<grid, block, smem_bytes>>>(
        x, conv_w, conv_b, ln_g, ln_b, pw_w, pw_b, out);
}